// round 14
// baseline (speedup 1.0000x reference)
#include <cuda_runtime.h>
#include <cstdint>

// ---- detect architecture-specific (sm_103a/sm_100a) compilation pass ----
#ifndef HAS_TC
#  if defined(__CUDA_ARCH_FEAT_SM103_ALL) || defined(__CUDA_ARCH_FEAT_SM100_ALL)
#    define HAS_TC 1
#  endif
#endif
#ifndef HAS_TC
#  ifdef __CUDA_ARCH_HAS_FEATURE__
#    if __CUDA_ARCH_HAS_FEATURE__(SM103_ALL) || __CUDA_ARCH_HAS_FEATURE__(SM100_ALL)
#      define HAS_TC 1
#    endif
#  endif
#endif
#ifndef HAS_TC
#  define HAS_TC 0
#endif

#define NTOK  8192
#define DIM_  2048
#define S_    2048
#define KVH_  8

// ---------------- tile config ----------------
// tcgen05 path: one CTA computes 256x256 via two M=128 cg1 MMAs sharing B.
// Stage (64 KB): [A0 16KB | A1 16KB | B 32KB] x 3 stages.
// Producers (warps 0-7): A via LDG + cvt.rna.tf32 + STS (fuses x rounding),
// B via cp.async. Warp 8: MMA consumer. Decoupled via mbarriers.
#define BK 32                      // floats per K step (128B rows)
#define STAGES 3
#define STAGE_BYTES 65536
#define A0_OFF 0
#define A1_OFF 16384
#define B_OFF  32768

#define SMEM_AOFF 1024
#define SMEM_REQ  (1024 + STAGES * STAGE_BYTES)   // 197632

#define NTHREADS 288               // 256 loaders + 1 MMA warp

#define TMEM_COLS 512
// cg1 idesc: c=F32, a=TF32, b=TF32, M=128, N=256, K-major both
#define IDESC ((1u << 4) | (2u << 7) | (2u << 10) | ((256 / 8) << 17) | ((128 / 16) << 24))

// ---------------- scratch ----------------
__device__ float g_w   [(size_t)(3072 + 2048) * DIM_];
__device__ float g_qkv [(size_t)NTOK * 3072];
__device__ float g_attn[(size_t)NTOK * DIM_];
#define WO_OFF ((size_t)3072 * DIM_)

// ---------------- helpers ----------------
__device__ __forceinline__ uint32_t smem_u32(const void* p) {
    return (uint32_t)__cvta_generic_to_shared(p);
}
__device__ __forceinline__ void cp_async16(uint32_t saddr, const void* gptr) {
    asm volatile("cp.async.cg.shared.global [%0], [%1], 16;\n" :: "r"(saddr), "l"(gptr));
}
__device__ __forceinline__ uint32_t swz128(uint32_t off) {
    return off ^ ((off >> 3) & 0x70);
}
__device__ __forceinline__ float round_tf32f(float f) {
    uint32_t u;
    asm("cvt.rna.tf32.f32 %0, %1;" : "=r"(u) : "f"(f));
    return __uint_as_float(u);
}
__device__ __forceinline__ float4 round_tf32f4(float4 v) {
    v.x = round_tf32f(v.x); v.y = round_tf32f(v.y);
    v.z = round_tf32f(v.z); v.w = round_tf32f(v.w);
    return v;
}
__device__ __forceinline__ uint32_t lds32(const char* smem, uint32_t off) {
    return *reinterpret_cast<const uint32_t*>(smem + off);
}
__device__ __forceinline__ void mma_tf32(float c[4], const uint32_t a[4], const uint32_t b[2]) {
    asm volatile(
        "mma.sync.aligned.m16n8k8.row.col.f32.tf32.tf32.f32 "
        "{%0,%1,%2,%3}, {%4,%5,%6,%7}, {%8,%9}, {%0,%1,%2,%3};"
        : "+f"(c[0]), "+f"(c[1]), "+f"(c[2]), "+f"(c[3])
        : "r"(a[0]), "r"(a[1]), "r"(a[2]), "r"(a[3]), "r"(b[0]), "r"(b[1]));
}

#define MBARRIER_INIT(addr, cnt) \
    asm volatile("mbarrier.init.shared.b64 [%0], %1;" :: "r"(addr), "r"(cnt) : "memory")

// plain arrive (release, cta scope): orders this thread's prior smem stores
#define MBARRIER_ARRIVE(addr) \
    asm volatile("mbarrier.arrive.shared.b64 _, [%0];" \
                 :: "r"((uint32_t)(addr)) : "memory")

#define MBARRIER_WAIT_PARITY(addr, ph) do {                                        \
    uint32_t _m = (addr); uint32_t _p = (ph); uint32_t _d;                         \
    asm volatile("{\n\t.reg .pred p;\n\t"                                          \
        "mbarrier.try_wait.parity.acquire.cta.shared::cta.b64 p, [%1], %2;\n\t"    \
        "selp.b32 %0, 1, 0, p;\n\t}"                                               \
        : "=r"(_d) : "r"(_m), "r"(_p) : "memory");                                 \
    if (!_d) {                                                                     \
        asm volatile("{\n\t.reg .pred P1;\n\t"                                     \
        "WL_%=:\n\t"                                                               \
        "mbarrier.try_wait.parity.acquire.cta.shared::cta.b64 P1, [%0], %1, 0x989680;\n\t" \
        "@P1 bra.uni WD_%=;\n\t"                                                   \
        "bra.uni WL_%=;\n\t"                                                       \
        "WD_%=:\n\t}" :: "r"(_m), "r"(_p) : "memory");                             \
    }                                                                              \
} while (0)

// .noinc: one true arrival per thread when its prior cp.asyncs complete
#define CP_ASYNC_MBAR_ARRIVE_NOINC(addr) \
    asm volatile("cp.async.mbarrier.arrive.noinc.shared::cta.b64 [%0];" \
                 :: "r"((uint32_t)(addr)) : "memory")

#if HAS_TC
#define TCGEN05_ALLOC(saddr, ncols) \
    asm volatile("tcgen05.alloc.cta_group::1.sync.aligned.shared::cta.b32 [%0], %1;" \
                 :: "r"((uint32_t)(saddr)), "r"((uint32_t)(ncols)) : "memory")
#define TCGEN05_RELINQ() \
    asm volatile("tcgen05.relinquish_alloc_permit.cta_group::1.sync.aligned;")
#define TCGEN05_DEALLOC(tmem, ncols) \
    asm volatile("tcgen05.dealloc.cta_group::1.sync.aligned.b32 %0, %1;" \
                 :: "r"(tmem), "r"((uint32_t)(ncols)))
#define TCGEN05_COMMIT(mbar) \
    asm volatile("tcgen05.commit.cta_group::1.mbarrier::arrive::one.shared::cluster.b64 [%0];" \
                 :: "r"((uint32_t)(mbar)) : "memory")
#define TCGEN05_FENCE_AFTER()  asm volatile("tcgen05.fence::after_thread_sync;" ::: "memory")
#define TCGEN05_FENCE_BEFORE() asm volatile("tcgen05.fence::before_thread_sync;" ::: "memory")
#define TCGEN05_WAIT_LD()      asm volatile("tcgen05.wait::ld.sync.aligned;" ::: "memory")
#define FENCE_PROXY_ASYNC()    asm volatile("fence.proxy.async.shared::cta;" ::: "memory")

#define TCGEN05_LD_X32(r, taddr) \
    asm volatile("tcgen05.ld.sync.aligned.32x32b.x32.b32 " \
        "{%0, %1, %2, %3, %4, %5, %6, %7, %8, %9, %10, %11, %12, %13, %14, %15, " \
        " %16, %17, %18, %19, %20, %21, %22, %23, %24, %25, %26, %27, %28, %29, %30, %31}, [%32];" \
        : "=r"((r)[0]), "=r"((r)[1]), "=r"((r)[2]), "=r"((r)[3]),      \
          "=r"((r)[4]), "=r"((r)[5]), "=r"((r)[6]), "=r"((r)[7]),      \
          "=r"((r)[8]), "=r"((r)[9]), "=r"((r)[10]), "=r"((r)[11]),    \
          "=r"((r)[12]), "=r"((r)[13]), "=r"((r)[14]), "=r"((r)[15]),  \
          "=r"((r)[16]), "=r"((r)[17]), "=r"((r)[18]), "=r"((r)[19]),  \
          "=r"((r)[20]), "=r"((r)[21]), "=r"((r)[22]), "=r"((r)[23]),  \
          "=r"((r)[24]), "=r"((r)[25]), "=r"((r)[26]), "=r"((r)[27]),  \
          "=r"((r)[28]), "=r"((r)[29]), "=r"((r)[30]), "=r"((r)[31])   \
        : "r"(taddr))

static constexpr uint64_t SMEM_DESC_BASE_SW128 =
    (uint64_t(2) << 61) | (uint64_t(1) << 46) | (uint64_t(64) << 32) | (uint64_t(1) << 16);
#define MAKE_SMEM_DESC(addr) (SMEM_DESC_BASE_SW128 | ((uint64_t)((addr) >> 4) & 0x3FFF))

__device__ __forceinline__ void mma_tf32_ss(uint32_t d_tmem, uint64_t a_desc,
                                            uint64_t b_desc, uint32_t idesc, bool acc) {
    uint32_t en = acc ? 1u : 0u;
    asm volatile(
        "{\n\t.reg .pred p;\n\t"
        "setp.ne.u32 p, %4, 0;\n\t"
        "tcgen05.mma.cta_group::1.kind::tf32 [%0], %1, %2, %3, {%5, %5, %5, %5}, p;\n\t}"
        :: "r"(d_tmem), "l"(a_desc), "l"(b_desc), "r"(idesc), "r"(en), "r"(0u)
        : "memory");
}
#endif  // HAS_TC

// ---------------- tf32 pre-rounding (weights only; x is rounded in-GEMM) ----------------
__global__ void round_w4(const float4* __restrict__ wq, const float4* __restrict__ wk,
                         const float4* __restrict__ wv, const float4* __restrict__ wo,
                         float4* __restrict__ out) {
    const int i = blockIdx.x * blockDim.x + threadIdx.x;   // float4 index
    const int Q4  = 2048 * 2048 / 4;   // 1048576
    const int K4  = 512 * 2048 / 4;    // 262144
    const float4* src;
    int idx;
    if (i < Q4)                { src = wq; idx = i; }
    else if (i < Q4 + K4)      { src = wk; idx = i - Q4; }
    else if (i < Q4 + 2 * K4)  { src = wv; idx = i - Q4 - K4; }
    else                       { src = wo; idx = i - Q4 - 2 * K4; }
    out[i] = round_tf32f4(src[idx]);
}

// ---------------- GEMM: C[M,ldc] = A[M,K] * B[N,K]^T ----------------
// grid = (N/256, M/256), block = 288. B must be tf32-pre-rounded; A may be
// raw fp32 (producers apply cvt.rna.tf32 in-flight).
__global__ void __launch_bounds__(NTHREADS, 1)
gemm_tc(const float* __restrict__ A, const float* __restrict__ Bm,
        float* __restrict__ C, int K, int ldc) {
    extern __shared__ char smem[];
    const uint32_t sbase = smem_u32(smem);
    const int tid = threadIdx.x;
    const int wid = tid >> 5, lid = tid & 31;
    const int bmp = blockIdx.y * 256;
    const int bn  = blockIdx.x * 256;
    const int KT = K / BK;

    const int r0 = (tid & 255) >> 3;    // 0..31
    const int cb = (tid & 7) * 16;      // byte col within 128B row

#if HAS_TC
    // ======== tcgen05 path ========
    const float* A0g = A  + (size_t)bmp * K;
    const float* A1g = A  + (size_t)(bmp + 128) * K;
    const float* Bg0 = Bm + (size_t)bn * K;

    const uint32_t EMPTY_BAR  = sbase + 16;    // STAGES bars (count 1, MMA commit)
    const uint32_t FULL_A_BAR = sbase + 64;    // STAGES bars (count 256, STS arrivals)
    const uint32_t FULL_B_BAR = sbase + 96;    // STAGES bars (count 256, cp.async noinc)
    const uint32_t DONE_BAR   = sbase + 128;

    if (wid == 8) TCGEN05_ALLOC(sbase, TMEM_COLS);
    if (tid == 0) {
        #pragma unroll
        for (int s = 0; s < STAGES; s++) {
            MBARRIER_INIT(EMPTY_BAR + s * 8, 1);
            MBARRIER_INIT(FULL_A_BAR + s * 8, 256);
            MBARRIER_INIT(FULL_B_BAR + s * 8, 256);
        }
        MBARRIER_INIT(DONE_BAR, 1);
    }
    __syncthreads();
    if (wid == 8) TCGEN05_RELINQ();

    uint32_t tmem;
    asm volatile("ld.shared.b32 %0, [%1];" : "=r"(tmem) : "r"(sbase));
    const uint32_t D0 = tmem, D1 = tmem + 256;

    if (tid < 256) {
        // ---- producers ----
        for (int j = 0; j < KT; j++) {
            const int s = j % STAGES;
            if (j >= STAGES) {
                int ph = ((j / STAGES) - 1) & 1;
                MBARRIER_WAIT_PARITY(EMPTY_BAR + s * 8, ph);
            }
            const uint32_t st = sbase + SMEM_AOFF + s * STAGE_BYTES;
            const size_t kof = (size_t)j * BK + (cb >> 2);

            // B via cp.async (pre-rounded weights)
            #pragma unroll
            for (int r = 0; r < 256; r += 32) {
                int row = r + r0;
                cp_async16(st + B_OFF + swz128(row * 128 + cb),
                           Bg0 + (size_t)row * K + kof);
            }

            // A via LDG (raw fp32) -> cvt.rna.tf32 -> STS (rounding fused)
            float4 va[8];
            #pragma unroll
            for (int r = 0; r < 4; r++)
                va[r] = *reinterpret_cast<const float4*>(
                    A0g + (size_t)(r * 32 + r0) * K + kof);
            #pragma unroll
            for (int r = 0; r < 4; r++)
                va[4 + r] = *reinterpret_cast<const float4*>(
                    A1g + (size_t)(r * 32 + r0) * K + kof);
            char* stc = smem + SMEM_AOFF + s * STAGE_BYTES;
            #pragma unroll
            for (int r = 0; r < 4; r++) {
                uint32_t so = swz128((r * 32 + r0) * 128 + cb);
                *reinterpret_cast<float4*>(stc + A0_OFF + so) = round_tf32f4(va[r]);
                *reinterpret_cast<float4*>(stc + A1_OFF + so) = round_tf32f4(va[4 + r]);
            }

            MBARRIER_ARRIVE(FULL_A_BAR + s * 8);            // release: orders STS
            CP_ASYNC_MBAR_ARRIVE_NOINC(FULL_B_BAR + s * 8); // fires when B lands
        }
    } else if (tid == 256) {
        // ---- MMA consumer ----
        for (int kt = 0; kt < KT; kt++) {
            const int s = kt % STAGES;
            const int ph = (kt / STAGES) & 1;
            MBARRIER_WAIT_PARITY(FULL_A_BAR + s * 8, ph);
            MBARRIER_WAIT_PARITY(FULL_B_BAR + s * 8, ph);
            FENCE_PROXY_ASYNC();
            const uint32_t st = sbase + SMEM_AOFF + s * STAGE_BYTES;
            uint64_t a0 = MAKE_SMEM_DESC(st + A0_OFF);
            uint64_t a1 = MAKE_SMEM_DESC(st + A1_OFF);
            uint64_t bd = MAKE_SMEM_DESC(st + B_OFF);
            bool acc0 = (kt > 0);
            #pragma unroll
            for (int k = 0; k < 4; k++) {
                mma_tf32_ss(D0, a0 + k * 2, bd + k * 2, IDESC, acc0 || (k > 0));
                mma_tf32_ss(D1, a1 + k * 2, bd + k * 2, IDESC, acc0 || (k > 0));
            }
            TCGEN05_COMMIT(EMPTY_BAR + s * 8);
        }
        TCGEN05_COMMIT(DONE_BAR);
    }

    MBARRIER_WAIT_PARITY(DONE_BAR, 0);
    TCGEN05_FENCE_AFTER();

    // epilogue: warps 0-3 -> D0 (rows bmp+0..127), warps 4-7 -> D1 (rows +128)
    if (wid < 8) {
        const int row = bmp + (wid >> 2) * 128 + (wid & 3) * 32 + lid;
        const uint32_t dT = (wid >> 2) ? D1 : D0;
        float* crow = C + (size_t)row * ldc + bn;
        #pragma unroll
        for (int c2 = 0; c2 < 256; c2 += 32) {
            uint32_t r[32];
            TCGEN05_LD_X32(r, dT + c2);
            TCGEN05_WAIT_LD();
            #pragma unroll
            for (int q = 0; q < 32; q += 4) {
                float4 v = make_float4(__uint_as_float(r[q]), __uint_as_float(r[q + 1]),
                                       __uint_as_float(r[q + 2]), __uint_as_float(r[q + 3]));
                *reinterpret_cast<float4*>(crow + c2 + q) = v;
            }
        }
    }
    TCGEN05_FENCE_BEFORE();
    __syncthreads();
    if (wid == 8) TCGEN05_DEALLOC(tmem, TMEM_COLS);

#else
    // ======== legacy mma.sync fallback: 256x256 tile in two sequential halves ========
    const int wr = (wid & 7) >> 2, wc = wid & 3;
    const int grp = lid >> 2, tig = lid & 3;

    for (int half = 0; half < 2; half++) {
        const int bm = bmp + half * 128;

        auto issue_loads = [&](int j) {
            const int s = j % STAGES;
            char* stc = smem + SMEM_AOFF + s * STAGE_BYTES;
            const uint32_t st = sbase + SMEM_AOFF + s * STAGE_BYTES;
            const float* Ag = A  + (size_t)bm * K + (size_t)j * BK;
            const float* Bg = Bm + (size_t)bn * K + (size_t)j * BK;
            // A: LDG + round + STS (fuses x rounding)
            #pragma unroll
            for (int r = 0; r < 128; r += 32) {
                int row = r + r0;
                float4 v = *reinterpret_cast<const float4*>(Ag + (size_t)row * K + (cb >> 2));
                *reinterpret_cast<float4*>(stc + A0_OFF + swz128(row * 128 + cb)) =
                    round_tf32f4(v);
            }
            // B: cp.async (pre-rounded)
            #pragma unroll
            for (int r = 0; r < 256; r += 32) {
                int row = r + r0;
                cp_async16(st + B_OFF + swz128(row * 128 + cb), Bg + (size_t)row * K + (cb >> 2));
            }
        };

        float acc[4][8][4];
        #pragma unroll
        for (int i = 0; i < 4; i++)
            #pragma unroll
            for (int j2 = 0; j2 < 8; j2++)
                #pragma unroll
                for (int r = 0; r < 4; r++) acc[i][j2][r] = 0.f;

        auto compute = [&](int s) {
            const char* st = smem + SMEM_AOFF + s * STAGE_BYTES;
            const char* as = st + A0_OFF;
            const char* bs = st + B_OFF;
            #pragma unroll
            for (int kk = 0; kk < BK; kk += 8) {
                uint32_t af[4][4], bf[8][2];
                #pragma unroll
                for (int mt = 0; mt < 4; mt++) {
                    int rb = wr * 64 + mt * 16;
                    af[mt][0] = lds32(as, swz128((rb + grp)     * 128 + (kk + tig) * 4));
                    af[mt][1] = lds32(as, swz128((rb + grp + 8) * 128 + (kk + tig) * 4));
                    af[mt][2] = lds32(as, swz128((rb + grp)     * 128 + (kk + tig + 4) * 4));
                    af[mt][3] = lds32(as, swz128((rb + grp + 8) * 128 + (kk + tig + 4) * 4));
                }
                #pragma unroll
                for (int nt = 0; nt < 8; nt++) {
                    int cbn = wc * 64 + nt * 8;
                    bf[nt][0] = lds32(bs, swz128((cbn + grp) * 128 + (kk + tig) * 4));
                    bf[nt][1] = lds32(bs, swz128((cbn + grp) * 128 + (kk + tig + 4) * 4));
                }
                #pragma unroll
                for (int mt = 0; mt < 4; mt++)
                    #pragma unroll
                    for (int nt = 0; nt < 8; nt++)
                        mma_tf32(acc[mt][nt], af[mt], bf[nt]);
            }
        };

        #pragma unroll
        for (int j = 0; j < STAGES - 1; j++) {
            if (tid < 256) issue_loads(j);
            asm volatile("cp.async.commit_group;\n" ::);
        }
        asm volatile("cp.async.wait_group %0;\n" :: "n"(STAGES - 2));
        __syncthreads();

        for (int kt = 0; kt < KT; kt++) {
            int j = kt + STAGES - 1;
            if (j < KT && tid < 256) issue_loads(j);
            asm volatile("cp.async.commit_group;\n" ::);
            if (tid < 256) compute(kt % STAGES);
            asm volatile("cp.async.wait_group %0;\n" :: "n"(STAGES - 2));
            __syncthreads();
        }

        if (tid < 256) {
            #pragma unroll
            for (int mt = 0; mt < 4; mt++) {
                #pragma unroll
                for (int nt = 0; nt < 8; nt++) {
                    int row = bm + wr * 64 + mt * 16 + grp;
                    int col = bn + wc * 64 + nt * 8 + tig * 2;
                    *reinterpret_cast<float2*>(C + (size_t)row * ldc + col) =
                        make_float2(acc[mt][nt][0], acc[mt][nt][1]);
                    *reinterpret_cast<float2*>(C + (size_t)(row + 8) * ldc + col) =
                        make_float2(acc[mt][nt][2], acc[mt][nt][3]);
                }
            }
        }
        __syncthreads();
    }
#endif
}

// ---------------- per-token attention (RoPE-free; 8 tokens/block, cp.async pipelined) ----------------
// qkv row layout: [q(2048) | k(512) | v(512)].
// RoPE cancels in q.k at equal positions; softmax over 32 repeated heads == over 8 KV heads.
#define PADR 68
#define ATOK 8
#define TOKF (32 * PADR + 2 * KVH_ * PADR)   // 3264 floats per token buffer
#define QOFF 0
#define KOFF (32 * PADR)
#define VOFF (32 * PADR + KVH_ * PADR)

__global__ void __launch_bounds__(256)
attn_kernel(const float* __restrict__ qkv, float* __restrict__ attn_out) {
    __shared__ float buf[2][TOKF];
    __shared__ float w_s[32][9];

    const int tid = threadIdx.x;
    const int t0  = blockIdx.x * ATOK;
    const uint32_t sb = smem_u32(buf);

    auto load_tok = [&](int t, int s) {
        const float* src = qkv + (size_t)t * 3072;
        #pragma unroll
        for (int r = 0; r < 3; r++) {
            int c = tid + 256 * r;
            uint32_t off;
            if (c < 512) {
                int row = c >> 4, col = c & 15;
                off = QOFF + row * PADR + col * 4;
            } else {
                int l = c - 512;
                int row = (l & 127) >> 4, col = l & 15;
                off = ((l < 128) ? KOFF : VOFF) + row * PADR + col * 4;
            }
            cp_async16(sb + (s * TOKF + off) * 4, src + c * 4);
        }
        asm volatile("cp.async.commit_group;\n" ::);
    };

    load_tok(t0, 0);

    for (int i = 0; i < ATOK; i++) {
        const int s = i & 1;
        if (i + 1 < ATOK) {
            load_tok(t0 + i + 1, s ^ 1);
            asm volatile("cp.async.wait_group %0;\n" :: "n"(1));
        } else {
            asm volatile("cp.async.wait_group %0;\n" :: "n"(0));
        }
        __syncthreads();

        const int t = t0 + i;
        const int h = tid >> 3, j = tid & 7;

        {
            const float* qh = &buf[s][QOFF + h * PADR];
            const float* kj = &buf[s][KOFF + j * PADR];
            float acc = 0.f;
            #pragma unroll
            for (int ii = 0; ii < 16; ii++) {
                float4 a = *reinterpret_cast<const float4*>(qh + ii * 4);
                float4 b = *reinterpret_cast<const float4*>(kj + ii * 4);
                acc += a.x * b.x + a.y * b.y + a.z * b.z + a.w * b.w;
            }
            float sc = acc * 0.125f;   // HD^-0.5

            float m = sc;
            #pragma unroll
            for (int o = 4; o > 0; o >>= 1)
                m = fmaxf(m, __shfl_xor_sync(0xffffffffu, m, o));
            float e = __expf(sc - m);
            float sum = e;
            #pragma unroll
            for (int o = 4; o > 0; o >>= 1)
                sum += __shfl_xor_sync(0xffffffffu, sum, o);
            w_s[h][j] = e / sum;
        }
        __syncthreads();

        {
            const int dg = tid & 7;
            const int d0 = dg * 8;
            float wv[KVH_];
            #pragma unroll
            for (int jj = 0; jj < KVH_; jj++) wv[jj] = w_s[h][jj];

            float4 o0 = make_float4(0.f, 0.f, 0.f, 0.f);
            float4 o1 = make_float4(0.f, 0.f, 0.f, 0.f);
            #pragma unroll
            for (int jj = 0; jj < KVH_; jj++) {
                const float* vj = &buf[s][VOFF + jj * PADR + d0];
                float4 v0 = *reinterpret_cast<const float4*>(vj);
                float4 v1 = *reinterpret_cast<const float4*>(vj + 4);
                float w = wv[jj];
                o0.x += w * v0.x; o0.y += w * v0.y; o0.z += w * v0.z; o0.w += w * v0.w;
                o1.x += w * v1.x; o1.y += w * v1.y; o1.z += w * v1.z; o1.w += w * v1.w;
            }
            o0 = round_tf32f4(o0);
            o1 = round_tf32f4(o1);
            float4* og = reinterpret_cast<float4*>(attn_out + (size_t)t * 2048 + h * 64 + d0);
            og[0] = o0;
            og[1] = o1;
        }
        __syncthreads();
    }
}

// ---------------- launch ----------------
extern "C" void kernel_launch(void* const* d_in, const int* in_sizes, int n_in,
                              void* d_out, int out_size) {
    const float* x  = (const float*)d_in[0];
    const float* wq = (const float*)d_in[1];
    const float* wk = (const float*)d_in[2];
    const float* wv = (const float*)d_in[3];
    const float* wo = (const float*)d_in[4];
    float* out = (float*)d_out;

    float *w, *qkv, *attn;
    cudaGetSymbolAddress((void**)&w,    g_w);
    cudaGetSymbolAddress((void**)&qkv,  g_qkv);
    cudaGetSymbolAddress((void**)&attn, g_attn);

    cudaFuncSetAttribute(gemm_tc, cudaFuncAttributeMaxDynamicSharedMemorySize, SMEM_REQ);

    // pre-round the weights to tf32 (RNA); x is rounded in-flight by the GEMM producers
    {
        int w4 = (int)((size_t)(3072 + 2048) * DIM_ / 4);
        round_w4<<<(w4 + 255) / 256, 256>>>((const float4*)wq, (const float4*)wk,
                                            (const float4*)wv, (const float4*)wo,
                                            (float4*)w);
    }

    // fused QKV projection: [8192,2048] x [3072,2048]^T -> [8192,3072]  (A = raw x)
    gemm_tc<<<dim3(3072 / 256, NTOK / 256), NTHREADS, SMEM_REQ>>>(x, w, qkv, DIM_, 3072);

    // per-token attention (RoPE cancels at equal positions; output tf32-rounded)
    attn_kernel<<<NTOK / ATOK, 256>>>(qkv, attn);

    // output projection: [8192,2048] x [2048,2048]^T -> [8192,2048]
    gemm_tc<<<dim3(DIM_ / 256, NTOK / 256), NTHREADS, SMEM_REQ>>>(attn, w + WO_OFF, out, DIM_, DIM_);
}

// round 15
// speedup vs baseline: 1.2537x; 1.2537x over previous
#include <cuda_runtime.h>
#include <cstdint>

// ---- detect architecture-specific (sm_103a/sm_100a) compilation pass ----
#ifndef HAS_TC
#  if defined(__CUDA_ARCH_FEAT_SM103_ALL) || defined(__CUDA_ARCH_FEAT_SM100_ALL)
#    define HAS_TC 1
#  endif
#endif
#ifndef HAS_TC
#  ifdef __CUDA_ARCH_HAS_FEATURE__
#    if __CUDA_ARCH_HAS_FEATURE__(SM103_ALL) || __CUDA_ARCH_HAS_FEATURE__(SM100_ALL)
#      define HAS_TC 1
#    endif
#  endif
#endif
#ifndef HAS_TC
#  define HAS_TC 0
#endif

#define NTOK  8192
#define DIM_  2048
#define S_    2048
#define KVH_  8

// ---------------- tile config ----------------
#define BK 32                      // floats per K step (128B rows)
#define STAGES 3
#define STAGE_BYTES 65536
#define A0_OFF 0
#define A1_OFF 16384
#define B_OFF  32768

#define SMEM_AOFF 1024
#define SMEM_REQ  (1024 + STAGES * STAGE_BYTES)   // 197632

#define NTHREADS 288               // 256 loaders + 1 MMA warp

#define TMEM_COLS 512
// cg1 idesc: c=F32, a=TF32, b=TF32, M=128, N=256, K-major both
#define IDESC ((1u << 4) | (2u << 7) | (2u << 10) | ((256 / 8) << 17) | ((128 / 16) << 24))

// ---------------- scratch ----------------
__device__ float g_xr  [(size_t)NTOK * DIM_];
__device__ float g_w   [(size_t)(3072 + 2048) * DIM_];
__device__ float g_qkv [(size_t)NTOK * 3072];
__device__ float g_attn[(size_t)NTOK * DIM_];
#define WO_OFF ((size_t)3072 * DIM_)

// ---------------- helpers ----------------
__device__ __forceinline__ uint32_t smem_u32(const void* p) {
    return (uint32_t)__cvta_generic_to_shared(p);
}
__device__ __forceinline__ void cp_async16(uint32_t saddr, const void* gptr) {
    asm volatile("cp.async.cg.shared.global [%0], [%1], 16;\n" :: "r"(saddr), "l"(gptr));
}
__device__ __forceinline__ uint32_t swz128(uint32_t off) {
    return off ^ ((off >> 3) & 0x70);
}
__device__ __forceinline__ float round_tf32f(float f) {
    uint32_t u;
    asm("cvt.rna.tf32.f32 %0, %1;" : "=r"(u) : "f"(f));
    return __uint_as_float(u);
}
__device__ __forceinline__ uint32_t lds32(const char* smem, uint32_t off) {
    return *reinterpret_cast<const uint32_t*>(smem + off);
}
__device__ __forceinline__ void mma_tf32(float c[4], const uint32_t a[4], const uint32_t b[2]) {
    asm volatile(
        "mma.sync.aligned.m16n8k8.row.col.f32.tf32.tf32.f32 "
        "{%0,%1,%2,%3}, {%4,%5,%6,%7}, {%8,%9}, {%0,%1,%2,%3};"
        : "+f"(c[0]), "+f"(c[1]), "+f"(c[2]), "+f"(c[3])
        : "r"(a[0]), "r"(a[1]), "r"(a[2]), "r"(a[3]), "r"(b[0]), "r"(b[1]));
}

#define MBARRIER_INIT(addr, cnt) \
    asm volatile("mbarrier.init.shared.b64 [%0], %1;" :: "r"(addr), "r"(cnt) : "memory")

#define MBARRIER_WAIT_PARITY(addr, ph) do {                                        \
    uint32_t _m = (addr); uint32_t _p = (ph); uint32_t _d;                         \
    asm volatile("{\n\t.reg .pred p;\n\t"                                          \
        "mbarrier.try_wait.parity.acquire.cta.shared::cta.b64 p, [%1], %2;\n\t"    \
        "selp.b32 %0, 1, 0, p;\n\t}"                                               \
        : "=r"(_d) : "r"(_m), "r"(_p) : "memory");                                 \
    if (!_d) {                                                                     \
        asm volatile("{\n\t.reg .pred P1;\n\t"                                     \
        "WL_%=:\n\t"                                                               \
        "mbarrier.try_wait.parity.acquire.cta.shared::cta.b64 P1, [%0], %1, 0x989680;\n\t" \
        "@P1 bra.uni WD_%=;\n\t"                                                   \
        "bra.uni WL_%=;\n\t"                                                       \
        "WD_%=:\n\t}" :: "r"(_m), "r"(_p) : "memory");                             \
    }                                                                              \
} while (0)

// .noinc: one true arrival per thread when its prior cp.asyncs complete
#define CP_ASYNC_MBAR_ARRIVE_NOINC(addr) \
    asm volatile("cp.async.mbarrier.arrive.noinc.shared::cta.b64 [%0];" \
                 :: "r"((uint32_t)(addr)) : "memory")

#if HAS_TC
#define TCGEN05_ALLOC(saddr, ncols) \
    asm volatile("tcgen05.alloc.cta_group::1.sync.aligned.shared::cta.b32 [%0], %1;" \
                 :: "r"((uint32_t)(saddr)), "r"((uint32_t)(ncols)) : "memory")
#define TCGEN05_RELINQ() \
    asm volatile("tcgen05.relinquish_alloc_permit.cta_group::1.sync.aligned;")
#define TCGEN05_DEALLOC(tmem, ncols) \
    asm volatile("tcgen05.dealloc.cta_group::1.sync.aligned.b32 %0, %1;" \
                 :: "r"(tmem), "r"((uint32_t)(ncols)))
#define TCGEN05_COMMIT(mbar) \
    asm volatile("tcgen05.commit.cta_group::1.mbarrier::arrive::one.shared::cluster.b64 [%0];" \
                 :: "r"((uint32_t)(mbar)) : "memory")
#define TCGEN05_FENCE_AFTER()  asm volatile("tcgen05.fence::after_thread_sync;" ::: "memory")
#define TCGEN05_FENCE_BEFORE() asm volatile("tcgen05.fence::before_thread_sync;" ::: "memory")
#define TCGEN05_WAIT_LD()      asm volatile("tcgen05.wait::ld.sync.aligned;" ::: "memory")
#define FENCE_PROXY_ASYNC()    asm volatile("fence.proxy.async.shared::cta;" ::: "memory")

#define TCGEN05_LD_X32(r, taddr) \
    asm volatile("tcgen05.ld.sync.aligned.32x32b.x32.b32 " \
        "{%0, %1, %2, %3, %4, %5, %6, %7, %8, %9, %10, %11, %12, %13, %14, %15, " \
        " %16, %17, %18, %19, %20, %21, %22, %23, %24, %25, %26, %27, %28, %29, %30, %31}, [%32];" \
        : "=r"((r)[0]), "=r"((r)[1]), "=r"((r)[2]), "=r"((r)[3]),      \
          "=r"((r)[4]), "=r"((r)[5]), "=r"((r)[6]), "=r"((r)[7]),      \
          "=r"((r)[8]), "=r"((r)[9]), "=r"((r)[10]), "=r"((r)[11]),    \
          "=r"((r)[12]), "=r"((r)[13]), "=r"((r)[14]), "=r"((r)[15]),  \
          "=r"((r)[16]), "=r"((r)[17]), "=r"((r)[18]), "=r"((r)[19]),  \
          "=r"((r)[20]), "=r"((r)[21]), "=r"((r)[22]), "=r"((r)[23]),  \
          "=r"((r)[24]), "=r"((r)[25]), "=r"((r)[26]), "=r"((r)[27]),  \
          "=r"((r)[28]), "=r"((r)[29]), "=r"((r)[30]), "=r"((r)[31])   \
        : "r"(taddr))

static constexpr uint64_t SMEM_DESC_BASE_SW128 =
    (uint64_t(2) << 61) | (uint64_t(1) << 46) | (uint64_t(64) << 32) | (uint64_t(1) << 16);
#define MAKE_SMEM_DESC(addr) (SMEM_DESC_BASE_SW128 | ((uint64_t)((addr) >> 4) & 0x3FFF))

__device__ __forceinline__ void mma_tf32_ss(uint32_t d_tmem, uint64_t a_desc,
                                            uint64_t b_desc, uint32_t idesc, bool acc) {
    uint32_t en = acc ? 1u : 0u;
    asm volatile(
        "{\n\t.reg .pred p;\n\t"
        "setp.ne.u32 p, %4, 0;\n\t"
        "tcgen05.mma.cta_group::1.kind::tf32 [%0], %1, %2, %3, {%5, %5, %5, %5}, p;\n\t}"
        :: "r"(d_tmem), "l"(a_desc), "l"(b_desc), "r"(idesc), "r"(en), "r"(0u)
        : "memory");
}
#endif  // HAS_TC

// ---------------- tf32 pre-rounding ----------------
__global__ void round_k(const float4* __restrict__ in, float4* __restrict__ out, int n4) {
    int i = blockIdx.x * blockDim.x + threadIdx.x;
    if (i < n4) {
        float4 v = in[i];
        v.x = round_tf32f(v.x); v.y = round_tf32f(v.y);
        v.z = round_tf32f(v.z); v.w = round_tf32f(v.w);
        out[i] = v;
    }
}

// round all 4 weight matrices in one launch (wq 2048, wk 512, wv 512, wo 2048 rows x 2048)
__global__ void round_w4(const float4* __restrict__ wq, const float4* __restrict__ wk,
                         const float4* __restrict__ wv, const float4* __restrict__ wo,
                         float4* __restrict__ out) {
    const int i = blockIdx.x * blockDim.x + threadIdx.x;   // float4 index
    const int Q4  = 2048 * 2048 / 4;   // 1048576
    const int K4  = 512 * 2048 / 4;    // 262144
    const float4* src;
    int idx;
    if (i < Q4)                { src = wq; idx = i; }
    else if (i < Q4 + K4)      { src = wk; idx = i - Q4; }
    else if (i < Q4 + 2 * K4)  { src = wv; idx = i - Q4 - K4; }
    else                       { src = wo; idx = i - Q4 - 2 * K4; }
    float4 v = src[idx];
    v.x = round_tf32f(v.x); v.y = round_tf32f(v.y);
    v.z = round_tf32f(v.z); v.w = round_tf32f(v.w);
    out[i] = v;
}

// ---------------- GEMM: C[M,ldc] = A[M,K] * B[N,K]^T ----------------
// grid = (N/256, M/256), block = 288. Operands must be tf32-pre-rounded.
// Warps 0-7: producers (cp.async). Warp 8: MMA consumer. Decoupled via mbarriers.
__global__ void __launch_bounds__(NTHREADS, 1)
gemm_tc(const float* __restrict__ A, const float* __restrict__ Bm,
        float* __restrict__ C, int K, int ldc) {
    extern __shared__ char smem[];
    const uint32_t sbase = smem_u32(smem);
    const int tid = threadIdx.x;
    const int wid = tid >> 5, lid = tid & 31;
    const int bmp = blockIdx.y * 256;
    const int bn  = blockIdx.x * 256;
    const int KT = K / BK;

    const int r0 = (tid & 255) >> 3;    // 0..31
    const int cb = (tid & 7) * 16;      // byte col within 128B row

#if HAS_TC
    // ======== tcgen05 path ========
    const float* A0g = A  + (size_t)bmp * K;
    const float* A1g = A  + (size_t)(bmp + 128) * K;
    const float* Bg0 = Bm + (size_t)bn * K;

    auto issue_loads = [&](int j) {
        const int s = j % STAGES;
        const uint32_t st = sbase + SMEM_AOFF + s * STAGE_BYTES;
        const size_t kof = (size_t)j * BK + (cb >> 2);
        #pragma unroll
        for (int r = 0; r < 128; r += 32) {
            int row = r + r0;
            uint32_t so = swz128(row * 128 + cb);
            cp_async16(st + A0_OFF + so, A0g + (size_t)row * K + kof);
            cp_async16(st + A1_OFF + so, A1g + (size_t)row * K + kof);
        }
        #pragma unroll
        for (int r = 0; r < 256; r += 32) {
            int row = r + r0;
            cp_async16(st + B_OFF + swz128(row * 128 + cb), Bg0 + (size_t)row * K + kof);
        }
    };

    const uint32_t EMPTY_BAR = sbase + 16;     // STAGES bars (count 1, MMA commit)
    const uint32_t FULL_BAR  = sbase + 64;     // STAGES bars (count 256, loader arrivals)
    const uint32_t DONE_BAR  = sbase + 128;

    if (wid == 8) TCGEN05_ALLOC(sbase, TMEM_COLS);
    if (tid == 0) {
        #pragma unroll
        for (int s = 0; s < STAGES; s++) {
            MBARRIER_INIT(EMPTY_BAR + s * 8, 1);
            MBARRIER_INIT(FULL_BAR + s * 8, 256);
        }
        MBARRIER_INIT(DONE_BAR, 1);
    }
    __syncthreads();
    if (wid == 8) TCGEN05_RELINQ();

    uint32_t tmem;
    asm volatile("ld.shared.b32 %0, [%1];" : "=r"(tmem) : "r"(sbase));
    const uint32_t D0 = tmem, D1 = tmem + 256;

    if (tid < 256) {
        // ---- producers ----
        for (int j = 0; j < KT; j++) {
            if (j >= STAGES) {
                int ph = ((j / STAGES) - 1) & 1;
                MBARRIER_WAIT_PARITY(EMPTY_BAR + (j % STAGES) * 8, ph);
            }
            issue_loads(j);
            CP_ASYNC_MBAR_ARRIVE_NOINC(FULL_BAR + (j % STAGES) * 8);
        }
    } else if (tid == 256) {
        // ---- MMA consumer ----
        for (int kt = 0; kt < KT; kt++) {
            const int s = kt % STAGES;
            MBARRIER_WAIT_PARITY(FULL_BAR + s * 8, (kt / STAGES) & 1);
            FENCE_PROXY_ASYNC();
            const uint32_t st = sbase + SMEM_AOFF + s * STAGE_BYTES;
            uint64_t a0 = MAKE_SMEM_DESC(st + A0_OFF);
            uint64_t a1 = MAKE_SMEM_DESC(st + A1_OFF);
            uint64_t bd = MAKE_SMEM_DESC(st + B_OFF);
            bool acc0 = (kt > 0);
            #pragma unroll
            for (int k = 0; k < 4; k++) {
                mma_tf32_ss(D0, a0 + k * 2, bd + k * 2, IDESC, acc0 || (k > 0));
                mma_tf32_ss(D1, a1 + k * 2, bd + k * 2, IDESC, acc0 || (k > 0));
            }
            TCGEN05_COMMIT(EMPTY_BAR + s * 8);
        }
        TCGEN05_COMMIT(DONE_BAR);
    }

    MBARRIER_WAIT_PARITY(DONE_BAR, 0);
    TCGEN05_FENCE_AFTER();

    // epilogue: warps 0-3 -> D0 (rows bmp+0..127), warps 4-7 -> D1 (rows +128)
    if (wid < 8) {
        const int row = bmp + (wid >> 2) * 128 + (wid & 3) * 32 + lid;
        const uint32_t dT = (wid >> 2) ? D1 : D0;
        float* crow = C + (size_t)row * ldc + bn;
        #pragma unroll
        for (int c2 = 0; c2 < 256; c2 += 32) {
            uint32_t r[32];
            TCGEN05_LD_X32(r, dT + c2);
            TCGEN05_WAIT_LD();
            #pragma unroll
            for (int q = 0; q < 32; q += 4) {
                float4 v = make_float4(__uint_as_float(r[q]), __uint_as_float(r[q + 1]),
                                       __uint_as_float(r[q + 2]), __uint_as_float(r[q + 3]));
                *reinterpret_cast<float4*>(crow + c2 + q) = v;
            }
        }
    }
    TCGEN05_FENCE_BEFORE();
    __syncthreads();
    if (wid == 8) TCGEN05_DEALLOC(tmem, TMEM_COLS);

#else
    // ======== legacy mma.sync fallback: 256x256 tile in two sequential halves ========
    const int wr = (wid & 7) >> 2, wc = wid & 3;
    const int grp = lid >> 2, tig = lid & 3;

    for (int half = 0; half < 2; half++) {
        const int bm = bmp + half * 128;

        auto issue_loads = [&](int j) {
            const int s = j % STAGES;
            const uint32_t st = sbase + SMEM_AOFF + s * STAGE_BYTES;
            const float* Ag = A  + (size_t)bm * K + (size_t)j * BK;
            const float* Bg = Bm + (size_t)bn * K + (size_t)j * BK;
            #pragma unroll
            for (int r = 0; r < 128; r += 32) {
                int row = r + r0;
                cp_async16(st + A0_OFF + swz128(row * 128 + cb), Ag + (size_t)row * K + (cb >> 2));
            }
            #pragma unroll
            for (int r = 0; r < 256; r += 32) {
                int row = r + r0;
                cp_async16(st + B_OFF + swz128(row * 128 + cb), Bg + (size_t)row * K + (cb >> 2));
            }
        };

        float acc[4][8][4];
        #pragma unroll
        for (int i = 0; i < 4; i++)
            #pragma unroll
            for (int j2 = 0; j2 < 8; j2++)
                #pragma unroll
                for (int r = 0; r < 4; r++) acc[i][j2][r] = 0.f;

        auto compute = [&](int s) {
            const char* st = smem + SMEM_AOFF + s * STAGE_BYTES;
            const char* as = st + A0_OFF;
            const char* bs = st + B_OFF;
            #pragma unroll
            for (int kk = 0; kk < BK; kk += 8) {
                uint32_t af[4][4], bf[8][2];
                #pragma unroll
                for (int mt = 0; mt < 4; mt++) {
                    int rb = wr * 64 + mt * 16;
                    af[mt][0] = lds32(as, swz128((rb + grp)     * 128 + (kk + tig) * 4));
                    af[mt][1] = lds32(as, swz128((rb + grp + 8) * 128 + (kk + tig) * 4));
                    af[mt][2] = lds32(as, swz128((rb + grp)     * 128 + (kk + tig + 4) * 4));
                    af[mt][3] = lds32(as, swz128((rb + grp + 8) * 128 + (kk + tig + 4) * 4));
                }
                #pragma unroll
                for (int nt = 0; nt < 8; nt++) {
                    int cbn = wc * 64 + nt * 8;
                    bf[nt][0] = lds32(bs, swz128((cbn + grp) * 128 + (kk + tig) * 4));
                    bf[nt][1] = lds32(bs, swz128((cbn + grp) * 128 + (kk + tig + 4) * 4));
                }
                #pragma unroll
                for (int mt = 0; mt < 4; mt++)
                    #pragma unroll
                    for (int nt = 0; nt < 8; nt++)
                        mma_tf32(acc[mt][nt], af[mt], bf[nt]);
            }
        };

        #pragma unroll
        for (int j = 0; j < STAGES - 1; j++) {
            if (tid < 256) issue_loads(j);
            asm volatile("cp.async.commit_group;\n" ::);
        }
        asm volatile("cp.async.wait_group %0;\n" :: "n"(STAGES - 2));
        __syncthreads();

        for (int kt = 0; kt < KT; kt++) {
            int j = kt + STAGES - 1;
            if (j < KT && tid < 256) issue_loads(j);
            asm volatile("cp.async.commit_group;\n" ::);
            if (tid < 256) compute(kt % STAGES);
            asm volatile("cp.async.wait_group %0;\n" :: "n"(STAGES - 2));
            __syncthreads();
        }

        if (tid < 256) {
            #pragma unroll
            for (int mt = 0; mt < 4; mt++) {
                #pragma unroll
                for (int nt = 0; nt < 8; nt++) {
                    int row = bm + wr * 64 + mt * 16 + grp;
                    int col = bn + wc * 64 + nt * 8 + tig * 2;
                    *reinterpret_cast<float2*>(C + (size_t)row * ldc + col) =
                        make_float2(acc[mt][nt][0], acc[mt][nt][1]);
                    *reinterpret_cast<float2*>(C + (size_t)(row + 8) * ldc + col) =
                        make_float2(acc[mt][nt][2], acc[mt][nt][3]);
                }
            }
        }
        __syncthreads();
    }
#endif
}

// ---------------- per-token attention (RoPE-free; 8 tokens/block, cp.async pipelined) ----------------
// qkv row layout: [q(2048) | k(512) | v(512)].
// RoPE cancels in q.k at equal positions; softmax over 32 repeated heads == over 8 KV heads.
#define PADR 68
#define ATOK 8
#define TOKF (32 * PADR + 2 * KVH_ * PADR)   // 3264 floats per token buffer
#define QOFF 0
#define KOFF (32 * PADR)
#define VOFF (32 * PADR + KVH_ * PADR)

__global__ void __launch_bounds__(256)
attn_kernel(const float* __restrict__ qkv, float* __restrict__ attn_out) {
    __shared__ float buf[2][TOKF];
    __shared__ float w_s[32][9];

    const int tid = threadIdx.x;
    const int t0  = blockIdx.x * ATOK;
    const uint32_t sb = smem_u32(buf);

    auto load_tok = [&](int t, int s) {
        const float* src = qkv + (size_t)t * 3072;
        #pragma unroll
        for (int r = 0; r < 3; r++) {
            int c = tid + 256 * r;
            uint32_t off;
            if (c < 512) {
                int row = c >> 4, col = c & 15;
                off = QOFF + row * PADR + col * 4;
            } else {
                int l = c - 512;
                int row = (l & 127) >> 4, col = l & 15;
                off = ((l < 128) ? KOFF : VOFF) + row * PADR + col * 4;
            }
            cp_async16(sb + (s * TOKF + off) * 4, src + c * 4);
        }
        asm volatile("cp.async.commit_group;\n" ::);
    };

    load_tok(t0, 0);

    for (int i = 0; i < ATOK; i++) {
        const int s = i & 1;
        if (i + 1 < ATOK) {
            load_tok(t0 + i + 1, s ^ 1);
            asm volatile("cp.async.wait_group %0;\n" :: "n"(1));
        } else {
            asm volatile("cp.async.wait_group %0;\n" :: "n"(0));
        }
        __syncthreads();

        const int t = t0 + i;
        const int h = tid >> 3, j = tid & 7;

        {
            const float* qh = &buf[s][QOFF + h * PADR];
            const float* kj = &buf[s][KOFF + j * PADR];
            float acc = 0.f;
            #pragma unroll
            for (int ii = 0; ii < 16; ii++) {
                float4 a = *reinterpret_cast<const float4*>(qh + ii * 4);
                float4 b = *reinterpret_cast<const float4*>(kj + ii * 4);
                acc += a.x * b.x + a.y * b.y + a.z * b.z + a.w * b.w;
            }
            float sc = acc * 0.125f;   // HD^-0.5

            float m = sc;
            #pragma unroll
            for (int o = 4; o > 0; o >>= 1)
                m = fmaxf(m, __shfl_xor_sync(0xffffffffu, m, o));
            float e = __expf(sc - m);
            float sum = e;
            #pragma unroll
            for (int o = 4; o > 0; o >>= 1)
                sum += __shfl_xor_sync(0xffffffffu, sum, o);
            w_s[h][j] = e / sum;
        }
        __syncthreads();

        {
            const int dg = tid & 7;
            const int d0 = dg * 8;
            float wv[KVH_];
            #pragma unroll
            for (int jj = 0; jj < KVH_; jj++) wv[jj] = w_s[h][jj];

            float4 o0 = make_float4(0.f, 0.f, 0.f, 0.f);
            float4 o1 = make_float4(0.f, 0.f, 0.f, 0.f);
            #pragma unroll
            for (int jj = 0; jj < KVH_; jj++) {
                const float* vj = &buf[s][VOFF + jj * PADR + d0];
                float4 v0 = *reinterpret_cast<const float4*>(vj);
                float4 v1 = *reinterpret_cast<const float4*>(vj + 4);
                float w = wv[jj];
                o0.x += w * v0.x; o0.y += w * v0.y; o0.z += w * v0.z; o0.w += w * v0.w;
                o1.x += w * v1.x; o1.y += w * v1.y; o1.z += w * v1.z; o1.w += w * v1.w;
            }
            o0.x = round_tf32f(o0.x); o0.y = round_tf32f(o0.y);
            o0.z = round_tf32f(o0.z); o0.w = round_tf32f(o0.w);
            o1.x = round_tf32f(o1.x); o1.y = round_tf32f(o1.y);
            o1.z = round_tf32f(o1.z); o1.w = round_tf32f(o1.w);
            float4* og = reinterpret_cast<float4*>(attn_out + (size_t)t * 2048 + h * 64 + d0);
            og[0] = o0;
            og[1] = o1;
        }
        __syncthreads();
    }
}

// ---------------- launch ----------------
extern "C" void kernel_launch(void* const* d_in, const int* in_sizes, int n_in,
                              void* d_out, int out_size) {
    const float* x  = (const float*)d_in[0];
    const float* wq = (const float*)d_in[1];
    const float* wk = (const float*)d_in[2];
    const float* wv = (const float*)d_in[3];
    const float* wo = (const float*)d_in[4];
    float* out = (float*)d_out;

    float *xr, *w, *qkv, *attn;
    cudaGetSymbolAddress((void**)&xr,   g_xr);
    cudaGetSymbolAddress((void**)&w,    g_w);
    cudaGetSymbolAddress((void**)&qkv,  g_qkv);
    cudaGetSymbolAddress((void**)&attn, g_attn);

    cudaFuncSetAttribute(gemm_tc, cudaFuncAttributeMaxDynamicSharedMemorySize, SMEM_REQ);

    // pre-round all GEMM operands to tf32 (RNA) so HW truncation is lossless
    {
        int n4 = (int)((size_t)NTOK * DIM_ / 4);
        round_k<<<(n4 + 255) / 256, 256>>>((const float4*)x, (float4*)xr, n4);
        int w4 = (int)((size_t)(3072 + 2048) * DIM_ / 4);
        round_w4<<<(w4 + 255) / 256, 256>>>((const float4*)wq, (const float4*)wk,
                                            (const float4*)wv, (const float4*)wo,
                                            (float4*)w);
    }

    // fused QKV projection: [8192,2048] x [3072,2048]^T -> [8192,3072]
    gemm_tc<<<dim3(3072 / 256, NTOK / 256), NTHREADS, SMEM_REQ>>>(xr, w, qkv, DIM_, 3072);

    // per-token attention (RoPE cancels: rotations preserve same-position inner products)
    attn_kernel<<<NTOK / ATOK, 256>>>(qkv, attn);

    // output projection: [8192,2048] x [2048,2048]^T -> [8192,2048]
    gemm_tc<<<dim3(DIM_ / 256, NTOK / 256), NTHREADS, SMEM_REQ>>>(attn, w + WO_OFF, out, DIM_, DIM_);
}

// round 16
// speedup vs baseline: 1.3425x; 1.0708x over previous
#include <cuda_runtime.h>
#include <cstdint>

// ---- detect architecture-specific (sm_103a/sm_100a) compilation pass ----
#ifndef HAS_TC
#  if defined(__CUDA_ARCH_FEAT_SM103_ALL) || defined(__CUDA_ARCH_FEAT_SM100_ALL)
#    define HAS_TC 1
#  endif
#endif
#ifndef HAS_TC
#  ifdef __CUDA_ARCH_HAS_FEATURE__
#    if __CUDA_ARCH_HAS_FEATURE__(SM103_ALL) || __CUDA_ARCH_HAS_FEATURE__(SM100_ALL)
#      define HAS_TC 1
#    endif
#  endif
#endif
#ifndef HAS_TC
#  define HAS_TC 0
#endif

#define NTOK  8192
#define DIM_  2048
#define S_    2048
#define KVH_  8

// ---------------- tile config ----------------
#define BK 32                      // floats per K step (128B rows)
#define STAGES 3
#define STAGE_BYTES 65536
#define A0_OFF 0
#define A1_OFF 16384
#define B_OFF  32768

#define SMEM_AOFF 1024
#define SMEM_REQ  (1024 + STAGES * STAGE_BYTES)   // 197632

#define NTHREADS 288               // 256 loaders + 1 MMA warp

#define TMEM_COLS 512
// cg1 idesc: c=F32, a=TF32, b=TF32, M=128, N=256, K-major both
#define IDESC ((1u << 4) | (2u << 7) | (2u << 10) | ((256 / 8) << 17) | ((128 / 16) << 24))

// Compensation for A-side hardware truncation in the QKV GEMM:
// raw fp32 x truncated to tf32 shrinks by E[f/m] = 2^-11 * ln2 = 3.384e-4.
// Scaling wq/wk/wv by (1 + 3.384e-4) removes the systematic bias.
#define COMP 1.0003384f

// ---------------- scratch ----------------
__device__ float g_w   [(size_t)(3072 + 2048) * DIM_];
__device__ float g_qkv [(size_t)NTOK * 3072];
__device__ float g_attn[(size_t)NTOK * DIM_];
#define WO_OFF ((size_t)3072 * DIM_)

// ---------------- helpers ----------------
__device__ __forceinline__ uint32_t smem_u32(const void* p) {
    return (uint32_t)__cvta_generic_to_shared(p);
}
__device__ __forceinline__ void cp_async16(uint32_t saddr, const void* gptr) {
    asm volatile("cp.async.cg.shared.global [%0], [%1], 16;\n" :: "r"(saddr), "l"(gptr));
}
__device__ __forceinline__ uint32_t swz128(uint32_t off) {
    return off ^ ((off >> 3) & 0x70);
}
__device__ __forceinline__ float round_tf32f(float f) {
    uint32_t u;
    asm("cvt.rna.tf32.f32 %0, %1;" : "=r"(u) : "f"(f));
    return __uint_as_float(u);
}
__device__ __forceinline__ uint32_t lds32(const char* smem, uint32_t off) {
    return *reinterpret_cast<const uint32_t*>(smem + off);
}
__device__ __forceinline__ void mma_tf32(float c[4], const uint32_t a[4], const uint32_t b[2]) {
    asm volatile(
        "mma.sync.aligned.m16n8k8.row.col.f32.tf32.tf32.f32 "
        "{%0,%1,%2,%3}, {%4,%5,%6,%7}, {%8,%9}, {%0,%1,%2,%3};"
        : "+f"(c[0]), "+f"(c[1]), "+f"(c[2]), "+f"(c[3])
        : "r"(a[0]), "r"(a[1]), "r"(a[2]), "r"(a[3]), "r"(b[0]), "r"(b[1]));
}

#define MBARRIER_INIT(addr, cnt) \
    asm volatile("mbarrier.init.shared.b64 [%0], %1;" :: "r"(addr), "r"(cnt) : "memory")

#define MBARRIER_WAIT_PARITY(addr, ph) do {                                        \
    uint32_t _m = (addr); uint32_t _p = (ph); uint32_t _d;                         \
    asm volatile("{\n\t.reg .pred p;\n\t"                                          \
        "mbarrier.try_wait.parity.acquire.cta.shared::cta.b64 p, [%1], %2;\n\t"    \
        "selp.b32 %0, 1, 0, p;\n\t}"                                               \
        : "=r"(_d) : "r"(_m), "r"(_p) : "memory");                                 \
    if (!_d) {                                                                     \
        asm volatile("{\n\t.reg .pred P1;\n\t"                                     \
        "WL_%=:\n\t"                                                               \
        "mbarrier.try_wait.parity.acquire.cta.shared::cta.b64 P1, [%0], %1, 0x989680;\n\t" \
        "@P1 bra.uni WD_%=;\n\t"                                                   \
        "bra.uni WL_%=;\n\t"                                                       \
        "WD_%=:\n\t}" :: "r"(_m), "r"(_p) : "memory");                             \
    }                                                                              \
} while (0)

// .noinc: one true arrival per thread when its prior cp.asyncs complete
#define CP_ASYNC_MBAR_ARRIVE_NOINC(addr) \
    asm volatile("cp.async.mbarrier.arrive.noinc.shared::cta.b64 [%0];" \
                 :: "r"((uint32_t)(addr)) : "memory")

#if HAS_TC
#define TCGEN05_ALLOC(saddr, ncols) \
    asm volatile("tcgen05.alloc.cta_group::1.sync.aligned.shared::cta.b32 [%0], %1;" \
                 :: "r"((uint32_t)(saddr)), "r"((uint32_t)(ncols)) : "memory")
#define TCGEN05_RELINQ() \
    asm volatile("tcgen05.relinquish_alloc_permit.cta_group::1.sync.aligned;")
#define TCGEN05_DEALLOC(tmem, ncols) \
    asm volatile("tcgen05.dealloc.cta_group::1.sync.aligned.b32 %0, %1;" \
                 :: "r"(tmem), "r"((uint32_t)(ncols)))
#define TCGEN05_COMMIT(mbar) \
    asm volatile("tcgen05.commit.cta_group::1.mbarrier::arrive::one.shared::cluster.b64 [%0];" \
                 :: "r"((uint32_t)(mbar)) : "memory")
#define TCGEN05_FENCE_AFTER()  asm volatile("tcgen05.fence::after_thread_sync;" ::: "memory")
#define TCGEN05_FENCE_BEFORE() asm volatile("tcgen05.fence::before_thread_sync;" ::: "memory")
#define TCGEN05_WAIT_LD()      asm volatile("tcgen05.wait::ld.sync.aligned;" ::: "memory")
#define FENCE_PROXY_ASYNC()    asm volatile("fence.proxy.async.shared::cta;" ::: "memory")

#define TCGEN05_LD_X32(r, taddr) \
    asm volatile("tcgen05.ld.sync.aligned.32x32b.x32.b32 " \
        "{%0, %1, %2, %3, %4, %5, %6, %7, %8, %9, %10, %11, %12, %13, %14, %15, " \
        " %16, %17, %18, %19, %20, %21, %22, %23, %24, %25, %26, %27, %28, %29, %30, %31}, [%32];" \
        : "=r"((r)[0]), "=r"((r)[1]), "=r"((r)[2]), "=r"((r)[3]),      \
          "=r"((r)[4]), "=r"((r)[5]), "=r"((r)[6]), "=r"((r)[7]),      \
          "=r"((r)[8]), "=r"((r)[9]), "=r"((r)[10]), "=r"((r)[11]),    \
          "=r"((r)[12]), "=r"((r)[13]), "=r"((r)[14]), "=r"((r)[15]),  \
          "=r"((r)[16]), "=r"((r)[17]), "=r"((r)[18]), "=r"((r)[19]),  \
          "=r"((r)[20]), "=r"((r)[21]), "=r"((r)[22]), "=r"((r)[23]),  \
          "=r"((r)[24]), "=r"((r)[25]), "=r"((r)[26]), "=r"((r)[27]),  \
          "=r"((r)[28]), "=r"((r)[29]), "=r"((r)[30]), "=r"((r)[31])   \
        : "r"(taddr))

static constexpr uint64_t SMEM_DESC_BASE_SW128 =
    (uint64_t(2) << 61) | (uint64_t(1) << 46) | (uint64_t(64) << 32) | (uint64_t(1) << 16);
#define MAKE_SMEM_DESC(addr) (SMEM_DESC_BASE_SW128 | ((uint64_t)((addr) >> 4) & 0x3FFF))

__device__ __forceinline__ void mma_tf32_ss(uint32_t d_tmem, uint64_t a_desc,
                                            uint64_t b_desc, uint32_t idesc, bool acc) {
    uint32_t en = acc ? 1u : 0u;
    asm volatile(
        "{\n\t.reg .pred p;\n\t"
        "setp.ne.u32 p, %4, 0;\n\t"
        "tcgen05.mma.cta_group::1.kind::tf32 [%0], %1, %2, %3, {%5, %5, %5, %5}, p;\n\t}"
        :: "r"(d_tmem), "l"(a_desc), "l"(b_desc), "r"(idesc), "r"(en), "r"(0u)
        : "memory");
}
#endif  // HAS_TC

// ---------------- weight rounding (+ truncation-bias compensation) ----------------
// wq/wk/wv are scaled by COMP before RNA rounding: the QKV GEMM's A operand is
// raw fp32 x, which HW truncates to tf32 (systematic shrink 2^-11*ln2); the
// scale cancels that bias. wo is NOT scaled (GEMM2's A is RNA-rounded exactly).
__global__ void round_w4(const float4* __restrict__ wq, const float4* __restrict__ wk,
                         const float4* __restrict__ wv, const float4* __restrict__ wo,
                         float4* __restrict__ out) {
    const int i = blockIdx.x * blockDim.x + threadIdx.x;   // float4 index
    const int Q4  = 2048 * 2048 / 4;   // 1048576
    const int K4  = 512 * 2048 / 4;    // 262144
    const float4* src;
    int idx;
    float c;
    if (i < Q4)                { src = wq; idx = i;               c = COMP; }
    else if (i < Q4 + K4)      { src = wk; idx = i - Q4;          c = COMP; }
    else if (i < Q4 + 2 * K4)  { src = wv; idx = i - Q4 - K4;     c = COMP; }
    else                       { src = wo; idx = i - Q4 - 2 * K4; c = 1.0f; }
    float4 v = src[idx];
    v.x = round_tf32f(v.x * c); v.y = round_tf32f(v.y * c);
    v.z = round_tf32f(v.z * c); v.w = round_tf32f(v.w * c);
    out[i] = v;
}

// ---------------- GEMM: C[M,ldc] = A[M,K] * B[N,K]^T ----------------
// grid = (N/256, M/256), block = 288. B must be tf32-pre-rounded; A may be
// raw fp32 (HW truncates; bias compensated in B when A is raw).
// Warps 0-7: producers (cp.async). Warp 8: MMA consumer. Decoupled via mbarriers.
__global__ void __launch_bounds__(NTHREADS, 1)
gemm_tc(const float* __restrict__ A, const float* __restrict__ Bm,
        float* __restrict__ C, int K, int ldc) {
    extern __shared__ char smem[];
    const uint32_t sbase = smem_u32(smem);
    const int tid = threadIdx.x;
    const int wid = tid >> 5, lid = tid & 31;
    const int bmp = blockIdx.y * 256;
    const int bn  = blockIdx.x * 256;
    const int KT = K / BK;

    const int r0 = (tid & 255) >> 3;    // 0..31
    const int cb = (tid & 7) * 16;      // byte col within 128B row

#if HAS_TC
    // ======== tcgen05 path ========
    const float* A0g = A  + (size_t)bmp * K;
    const float* A1g = A  + (size_t)(bmp + 128) * K;
    const float* Bg0 = Bm + (size_t)bn * K;

    auto issue_loads = [&](int j) {
        const int s = j % STAGES;
        const uint32_t st = sbase + SMEM_AOFF + s * STAGE_BYTES;
        const size_t kof = (size_t)j * BK + (cb >> 2);
        #pragma unroll
        for (int r = 0; r < 128; r += 32) {
            int row = r + r0;
            uint32_t so = swz128(row * 128 + cb);
            cp_async16(st + A0_OFF + so, A0g + (size_t)row * K + kof);
            cp_async16(st + A1_OFF + so, A1g + (size_t)row * K + kof);
        }
        #pragma unroll
        for (int r = 0; r < 256; r += 32) {
            int row = r + r0;
            cp_async16(st + B_OFF + swz128(row * 128 + cb), Bg0 + (size_t)row * K + kof);
        }
    };

    const uint32_t EMPTY_BAR = sbase + 16;     // STAGES bars (count 1, MMA commit)
    const uint32_t FULL_BAR  = sbase + 64;     // STAGES bars (count 256, loader arrivals)
    const uint32_t DONE_BAR  = sbase + 128;

    if (wid == 8) TCGEN05_ALLOC(sbase, TMEM_COLS);
    if (tid == 0) {
        #pragma unroll
        for (int s = 0; s < STAGES; s++) {
            MBARRIER_INIT(EMPTY_BAR + s * 8, 1);
            MBARRIER_INIT(FULL_BAR + s * 8, 256);
        }
        MBARRIER_INIT(DONE_BAR, 1);
    }
    __syncthreads();
    if (wid == 8) TCGEN05_RELINQ();

    uint32_t tmem;
    asm volatile("ld.shared.b32 %0, [%1];" : "=r"(tmem) : "r"(sbase));
    const uint32_t D0 = tmem, D1 = tmem + 256;

    if (tid < 256) {
        // ---- producers ----
        for (int j = 0; j < KT; j++) {
            if (j >= STAGES) {
                int ph = ((j / STAGES) - 1) & 1;
                MBARRIER_WAIT_PARITY(EMPTY_BAR + (j % STAGES) * 8, ph);
            }
            issue_loads(j);
            CP_ASYNC_MBAR_ARRIVE_NOINC(FULL_BAR + (j % STAGES) * 8);
        }
    } else if (tid == 256) {
        // ---- MMA consumer ----
        for (int kt = 0; kt < KT; kt++) {
            const int s = kt % STAGES;
            MBARRIER_WAIT_PARITY(FULL_BAR + s * 8, (kt / STAGES) & 1);
            FENCE_PROXY_ASYNC();
            const uint32_t st = sbase + SMEM_AOFF + s * STAGE_BYTES;
            uint64_t a0 = MAKE_SMEM_DESC(st + A0_OFF);
            uint64_t a1 = MAKE_SMEM_DESC(st + A1_OFF);
            uint64_t bd = MAKE_SMEM_DESC(st + B_OFF);
            bool acc0 = (kt > 0);
            #pragma unroll
            for (int k = 0; k < 4; k++) {
                mma_tf32_ss(D0, a0 + k * 2, bd + k * 2, IDESC, acc0 || (k > 0));
                mma_tf32_ss(D1, a1 + k * 2, bd + k * 2, IDESC, acc0 || (k > 0));
            }
            TCGEN05_COMMIT(EMPTY_BAR + s * 8);
        }
        TCGEN05_COMMIT(DONE_BAR);
    }

    MBARRIER_WAIT_PARITY(DONE_BAR, 0);
    TCGEN05_FENCE_AFTER();

    // epilogue: warps 0-3 -> D0 (rows bmp+0..127), warps 4-7 -> D1 (rows +128)
    if (wid < 8) {
        const int row = bmp + (wid >> 2) * 128 + (wid & 3) * 32 + lid;
        const uint32_t dT = (wid >> 2) ? D1 : D0;
        float* crow = C + (size_t)row * ldc + bn;
        #pragma unroll
        for (int c2 = 0; c2 < 256; c2 += 32) {
            uint32_t r[32];
            TCGEN05_LD_X32(r, dT + c2);
            TCGEN05_WAIT_LD();
            #pragma unroll
            for (int q = 0; q < 32; q += 4) {
                float4 v = make_float4(__uint_as_float(r[q]), __uint_as_float(r[q + 1]),
                                       __uint_as_float(r[q + 2]), __uint_as_float(r[q + 3]));
                *reinterpret_cast<float4*>(crow + c2 + q) = v;
            }
        }
    }
    TCGEN05_FENCE_BEFORE();
    __syncthreads();
    if (wid == 8) TCGEN05_DEALLOC(tmem, TMEM_COLS);

#else
    // ======== legacy mma.sync fallback: 256x256 tile in two sequential halves ========
    const int wr = (wid & 7) >> 2, wc = wid & 3;
    const int grp = lid >> 2, tig = lid & 3;

    for (int half = 0; half < 2; half++) {
        const int bm = bmp + half * 128;

        auto issue_loads = [&](int j) {
            const int s = j % STAGES;
            const uint32_t st = sbase + SMEM_AOFF + s * STAGE_BYTES;
            const float* Ag = A  + (size_t)bm * K + (size_t)j * BK;
            const float* Bg = Bm + (size_t)bn * K + (size_t)j * BK;
            #pragma unroll
            for (int r = 0; r < 128; r += 32) {
                int row = r + r0;
                cp_async16(st + A0_OFF + swz128(row * 128 + cb), Ag + (size_t)row * K + (cb >> 2));
            }
            #pragma unroll
            for (int r = 0; r < 256; r += 32) {
                int row = r + r0;
                cp_async16(st + B_OFF + swz128(row * 128 + cb), Bg + (size_t)row * K + (cb >> 2));
            }
        };

        float acc[4][8][4];
        #pragma unroll
        for (int i = 0; i < 4; i++)
            #pragma unroll
            for (int j2 = 0; j2 < 8; j2++)
                #pragma unroll
                for (int r = 0; r < 4; r++) acc[i][j2][r] = 0.f;

        auto compute = [&](int s) {
            const char* st = smem + SMEM_AOFF + s * STAGE_BYTES;
            const char* as = st + A0_OFF;
            const char* bs = st + B_OFF;
            #pragma unroll
            for (int kk = 0; kk < BK; kk += 8) {
                uint32_t af[4][4], bf[8][2];
                #pragma unroll
                for (int mt = 0; mt < 4; mt++) {
                    int rb = wr * 64 + mt * 16;
                    af[mt][0] = lds32(as, swz128((rb + grp)     * 128 + (kk + tig) * 4));
                    af[mt][1] = lds32(as, swz128((rb + grp + 8) * 128 + (kk + tig) * 4));
                    af[mt][2] = lds32(as, swz128((rb + grp)     * 128 + (kk + tig + 4) * 4));
                    af[mt][3] = lds32(as, swz128((rb + grp + 8) * 128 + (kk + tig + 4) * 4));
                }
                #pragma unroll
                for (int nt = 0; nt < 8; nt++) {
                    int cbn = wc * 64 + nt * 8;
                    bf[nt][0] = lds32(bs, swz128((cbn + grp) * 128 + (kk + tig) * 4));
                    bf[nt][1] = lds32(bs, swz128((cbn + grp) * 128 + (kk + tig + 4) * 4));
                }
                #pragma unroll
                for (int mt = 0; mt < 4; mt++)
                    #pragma unroll
                    for (int nt = 0; nt < 8; nt++)
                        mma_tf32(acc[mt][nt], af[mt], bf[nt]);
            }
        };

        #pragma unroll
        for (int j = 0; j < STAGES - 1; j++) {
            if (tid < 256) issue_loads(j);
            asm volatile("cp.async.commit_group;\n" ::);
        }
        asm volatile("cp.async.wait_group %0;\n" :: "n"(STAGES - 2));
        __syncthreads();

        for (int kt = 0; kt < KT; kt++) {
            int j = kt + STAGES - 1;
            if (j < KT && tid < 256) issue_loads(j);
            asm volatile("cp.async.commit_group;\n" ::);
            if (tid < 256) compute(kt % STAGES);
            asm volatile("cp.async.wait_group %0;\n" :: "n"(STAGES - 2));
            __syncthreads();
        }

        if (tid < 256) {
            #pragma unroll
            for (int mt = 0; mt < 4; mt++) {
                #pragma unroll
                for (int nt = 0; nt < 8; nt++) {
                    int row = bm + wr * 64 + mt * 16 + grp;
                    int col = bn + wc * 64 + nt * 8 + tig * 2;
                    *reinterpret_cast<float2*>(C + (size_t)row * ldc + col) =
                        make_float2(acc[mt][nt][0], acc[mt][nt][1]);
                    *reinterpret_cast<float2*>(C + (size_t)(row + 8) * ldc + col) =
                        make_float2(acc[mt][nt][2], acc[mt][nt][3]);
                }
            }
        }
        __syncthreads();
    }
#endif
}

// ---------------- per-token attention (RoPE-free; 8 tokens/block, cp.async pipelined) ----------------
// qkv row layout: [q(2048) | k(512) | v(512)].
// RoPE cancels in q.k at equal positions; softmax over 32 repeated heads == over 8 KV heads.
#define PADR 68
#define ATOK 8
#define TOKF (32 * PADR + 2 * KVH_ * PADR)   // 3264 floats per token buffer
#define QOFF 0
#define KOFF (32 * PADR)
#define VOFF (32 * PADR + KVH_ * PADR)

__global__ void __launch_bounds__(256)
attn_kernel(const float* __restrict__ qkv, float* __restrict__ attn_out) {
    __shared__ float buf[2][TOKF];
    __shared__ float w_s[32][9];

    const int tid = threadIdx.x;
    const int t0  = blockIdx.x * ATOK;
    const uint32_t sb = smem_u32(buf);

    auto load_tok = [&](int t, int s) {
        const float* src = qkv + (size_t)t * 3072;
        #pragma unroll
        for (int r = 0; r < 3; r++) {
            int c = tid + 256 * r;
            uint32_t off;
            if (c < 512) {
                int row = c >> 4, col = c & 15;
                off = QOFF + row * PADR + col * 4;
            } else {
                int l = c - 512;
                int row = (l & 127) >> 4, col = l & 15;
                off = ((l < 128) ? KOFF : VOFF) + row * PADR + col * 4;
            }
            cp_async16(sb + (s * TOKF + off) * 4, src + c * 4);
        }
        asm volatile("cp.async.commit_group;\n" ::);
    };

    load_tok(t0, 0);

    for (int i = 0; i < ATOK; i++) {
        const int s = i & 1;
        if (i + 1 < ATOK) {
            load_tok(t0 + i + 1, s ^ 1);
            asm volatile("cp.async.wait_group %0;\n" :: "n"(1));
        } else {
            asm volatile("cp.async.wait_group %0;\n" :: "n"(0));
        }
        __syncthreads();

        const int t = t0 + i;
        const int h = tid >> 3, j = tid & 7;

        {
            const float* qh = &buf[s][QOFF + h * PADR];
            const float* kj = &buf[s][KOFF + j * PADR];
            float acc = 0.f;
            #pragma unroll
            for (int ii = 0; ii < 16; ii++) {
                float4 a = *reinterpret_cast<const float4*>(qh + ii * 4);
                float4 b = *reinterpret_cast<const float4*>(kj + ii * 4);
                acc += a.x * b.x + a.y * b.y + a.z * b.z + a.w * b.w;
            }
            float sc = acc * 0.125f;   // HD^-0.5

            float m = sc;
            #pragma unroll
            for (int o = 4; o > 0; o >>= 1)
                m = fmaxf(m, __shfl_xor_sync(0xffffffffu, m, o));
            float e = __expf(sc - m);
            float sum = e;
            #pragma unroll
            for (int o = 4; o > 0; o >>= 1)
                sum += __shfl_xor_sync(0xffffffffu, sum, o);
            w_s[h][j] = e / sum;
        }
        __syncthreads();

        {
            const int dg = tid & 7;
            const int d0 = dg * 8;
            float wv[KVH_];
            #pragma unroll
            for (int jj = 0; jj < KVH_; jj++) wv[jj] = w_s[h][jj];

            float4 o0 = make_float4(0.f, 0.f, 0.f, 0.f);
            float4 o1 = make_float4(0.f, 0.f, 0.f, 0.f);
            #pragma unroll
            for (int jj = 0; jj < KVH_; jj++) {
                const float* vj = &buf[s][VOFF + jj * PADR + d0];
                float4 v0 = *reinterpret_cast<const float4*>(vj);
                float4 v1 = *reinterpret_cast<const float4*>(vj + 4);
                float w = wv[jj];
                o0.x += w * v0.x; o0.y += w * v0.y; o0.z += w * v0.z; o0.w += w * v0.w;
                o1.x += w * v1.x; o1.y += w * v1.y; o1.z += w * v1.z; o1.w += w * v1.w;
            }
            o0.x = round_tf32f(o0.x); o0.y = round_tf32f(o0.y);
            o0.z = round_tf32f(o0.z); o0.w = round_tf32f(o0.w);
            o1.x = round_tf32f(o1.x); o1.y = round_tf32f(o1.y);
            o1.z = round_tf32f(o1.z); o1.w = round_tf32f(o1.w);
            float4* og = reinterpret_cast<float4*>(attn_out + (size_t)t * 2048 + h * 64 + d0);
            og[0] = o0;
            og[1] = o1;
        }
        __syncthreads();
    }
}

// ---------------- launch ----------------
extern "C" void kernel_launch(void* const* d_in, const int* in_sizes, int n_in,
                              void* d_out, int out_size) {
    const float* x  = (const float*)d_in[0];
    const float* wq = (const float*)d_in[1];
    const float* wk = (const float*)d_in[2];
    const float* wv = (const float*)d_in[3];
    const float* wo = (const float*)d_in[4];
    float* out = (float*)d_out;

    float *w, *qkv, *attn;
    cudaGetSymbolAddress((void**)&w,    g_w);
    cudaGetSymbolAddress((void**)&qkv,  g_qkv);
    cudaGetSymbolAddress((void**)&attn, g_attn);

    cudaFuncSetAttribute(gemm_tc, cudaFuncAttributeMaxDynamicSharedMemorySize, SMEM_REQ);

    // round weights to tf32 (RNA); wq/wk/wv carry the truncation-bias compensation
    {
        int w4 = (int)((size_t)(3072 + 2048) * DIM_ / 4);
        round_w4<<<(w4 + 255) / 256, 256>>>((const float4*)wq, (const float4*)wk,
                                            (const float4*)wv, (const float4*)wo,
                                            (float4*)w);
    }

    // fused QKV projection: [8192,2048] x [3072,2048]^T -> [8192,3072]
    // A = raw fp32 x (HW tf32 truncation; bias compensated in B)
    gemm_tc<<<dim3(3072 / 256, NTOK / 256), NTHREADS, SMEM_REQ>>>(x, w, qkv, DIM_, 3072);

    // per-token attention (RoPE cancels: rotations preserve same-position inner products)
    attn_kernel<<<NTOK / ATOK, 256>>>(qkv, attn);

    // output projection: [8192,2048] x [2048,2048]^T -> [8192,2048]
    // A = attn output (RNA-rounded in attn_kernel), B = wo (RNA, unscaled)
    gemm_tc<<<dim3(DIM_ / 256, NTOK / 256), NTHREADS, SMEM_REQ>>>(attn, w + WO_OFF, out, DIM_, DIM_);
}